// round 13
// baseline (speedup 1.0000x reference)
#include <cuda_runtime.h>
#include <math.h>
#include <stdint.h>

#define S_LEN   8192
#define E_DIM   1024
#define H_DIM   2048
#define T_TAGS  50

// ---------------- persistent recurrence config ----------------
#define RB_NBLK    128
#define RB_ROWS    16          // H rows per block (128*16 = 2048)
#define RB_THREADS 256         // 8 warps
#define N_GRP      8           // h chunks (one per warp)
#define GRP_CTAS   (RB_NBLK / N_GRP)    // 16 producer CTAs per chunk
#define CHUNK      (H_DIM / N_GRP)      // 256 floats per chunk

// ---------------- scratch (static device memory; no allocs) ----------------
__device__ float g_xi[(size_t)S_LEN * H_DIM];    // 64 MB
__device__ float g_rnn[(size_t)S_LEN * H_DIM];   // 64 MB
// packed epochs: group g's 16 producer words live in ONE 64B region at
// g_ep[g*32 .. g*32+15] (groups 128B apart). Single writer per word ->
// st.release (no RMW); consumer warp reads 16 consecutive words -> ONE
// coalesced transaction per poll iteration (the property R12 broke).
__device__ __align__(128) unsigned g_ep[N_GRP * 32];

__global__ void init_ep_kernel() {
    if (threadIdx.x < N_GRP * 32) g_ep[threadIdx.x] = 0u;
}

// ---------------- packed f32x2 helpers ----------------
__device__ __forceinline__ unsigned long long ffma2(unsigned long long a,
                                                    unsigned long long b,
                                                    unsigned long long c) {
    unsigned long long d;
    asm("fma.rn.f32x2 %0, %1, %2, %3;" : "=l"(d) : "l"(a), "l"(b), "l"(c));
    return d;
}
__device__ __forceinline__ unsigned long long addf2(unsigned long long a,
                                                    unsigned long long b) {
    unsigned long long d;
    asm("add.rn.f32x2 %0, %1, %2;" : "=l"(d) : "l"(a), "l"(b));
    return d;
}
// 64-bit shfl.xor via two 32-bit shfls
__device__ __forceinline__ unsigned long long shflx2(unsigned long long v,
                                                     int mask) {
    unsigned lo = (unsigned)v, hi = (unsigned)(v >> 32);
    lo = __shfl_xor_sync(0xffffffffu, lo, mask);
    hi = __shfl_xor_sync(0xffffffffu, hi, mask);
    return ((unsigned long long)hi << 32) | lo;
}

// fast tanh: 1 - 2/(e^{2x}+1); inf-safe, ~1e-6 rel err (budget is 1e-3)
__device__ __forceinline__ float tanh_fast(float x) {
    const float e2 = __expf(2.f * x);
    return 1.f - __fdividef(2.f, e2 + 1.f);
}

// ---------------- Kernel 1: fused embedding gather + xi GEMM (R3-proven) ----
#define GBM 64
#define GBN 64
#define GBK 16

__global__ __launch_bounds__(256) void xi_gemm_kernel(
    const int*   __restrict__ sent,
    const float* __restrict__ emb,
    const float* __restrict__ W_ih,
    const float* __restrict__ b_ih,
    const float* __restrict__ b_hh)
{
    __shared__ float As[GBM][GBK + 1];
    __shared__ float Bs[GBK][GBN + 4];
    __shared__ int   sidx[GBM];

    const int tid = threadIdx.x;
    const int m0  = blockIdx.y * GBM;
    const int n0  = blockIdx.x * GBN;

    if (tid < GBM) sidx[tid] = sent[m0 + tid];
    __syncthreads();

    const int lr = tid >> 2;
    const int lk = (tid & 3) * 4;
    const int tx = tid & 15;
    const int ty = tid >> 4;

    float acc[4][4];
#pragma unroll
    for (int i = 0; i < 4; i++)
#pragma unroll
        for (int j = 0; j < 4; j++) acc[i][j] = 0.f;

    const float* arow = emb  + (size_t)sidx[lr] * E_DIM;
    const float* brow = W_ih + (size_t)(n0 + lr) * E_DIM;

    for (int kt = 0; kt < E_DIM; kt += GBK) {
        float4 av = *(const float4*)(arow + kt + lk);
        float4 bv = *(const float4*)(brow + kt + lk);
        As[lr][lk + 0] = av.x; As[lr][lk + 1] = av.y;
        As[lr][lk + 2] = av.z; As[lr][lk + 3] = av.w;
        Bs[lk + 0][lr] = bv.x; Bs[lk + 1][lr] = bv.y;
        Bs[lk + 2][lr] = bv.z; Bs[lk + 3][lr] = bv.w;
        __syncthreads();

#pragma unroll
        for (int k = 0; k < GBK; k++) {
            float a0 = As[ty * 4 + 0][k];
            float a1 = As[ty * 4 + 1][k];
            float a2 = As[ty * 4 + 2][k];
            float a3 = As[ty * 4 + 3][k];
            float4 b4 = *(const float4*)&Bs[k][tx * 4];
            acc[0][0] = fmaf(a0, b4.x, acc[0][0]);
            acc[0][1] = fmaf(a0, b4.y, acc[0][1]);
            acc[0][2] = fmaf(a0, b4.z, acc[0][2]);
            acc[0][3] = fmaf(a0, b4.w, acc[0][3]);
            acc[1][0] = fmaf(a1, b4.x, acc[1][0]);
            acc[1][1] = fmaf(a1, b4.y, acc[1][1]);
            acc[1][2] = fmaf(a1, b4.z, acc[1][2]);
            acc[1][3] = fmaf(a1, b4.w, acc[1][3]);
            acc[2][0] = fmaf(a2, b4.x, acc[2][0]);
            acc[2][1] = fmaf(a2, b4.y, acc[2][1]);
            acc[2][2] = fmaf(a2, b4.z, acc[2][2]);
            acc[2][3] = fmaf(a2, b4.w, acc[2][3]);
            acc[3][0] = fmaf(a3, b4.x, acc[3][0]);
            acc[3][1] = fmaf(a3, b4.y, acc[3][1]);
            acc[3][2] = fmaf(a3, b4.z, acc[3][2]);
            acc[3][3] = fmaf(a3, b4.w, acc[3][3]);
        }
        __syncthreads();
    }

#pragma unroll
    for (int j = 0; j < 4; j++) {
        const int h = n0 + tx * 4 + j;
        const float bias = b_ih[h] + b_hh[h];
#pragma unroll
        for (int i = 0; i < 4; i++) {
            const int s = m0 + ty * 4 + i;
            g_xi[(size_t)s * H_DIM + h] = acc[i][j] + bias;
        }
    }
}

// ---------------- Kernel 2: persistent Elman recurrence ----------------
// Compute path identical to R11 (proven best). Sync: packed epoch line.
// Producer CTA b: ONE st.release.gpu to word [b>>4][b&15]. Consumer warp w:
// lane l ld.acquire's word (l>>1) of group w's 64B region — exactly the
// producer of lane l's 8 h rows (per-lane-exact pairing), 32 lanes -> 16
// consecutive words -> one coalesced transaction per poll iteration.
__global__ void __launch_bounds__(RB_THREADS, 1) rnn_kernel(
    const float* __restrict__ W_hh,
    const float* __restrict__ h0)
{
    __shared__ __align__(16) float part[2][N_GRP][16];  // double-buffered

    const int b    = blockIdx.x;
    const int tid  = threadIdx.x;
    const int warp = tid >> 5;
    const int lane = tid & 31;
    const int row0 = b * RB_ROWS;

    // ---- W registers: rows 0..15, cols warp*256 + lane*8 .. +7 ----
    unsigned long long W2[16][4];
    {
        const float* wb = W_hh + (size_t)row0 * H_DIM + warp * CHUNK + lane * 8;
#pragma unroll
        for (int r = 0; r < 16; r++) {
            ulonglong2 u = *(const ulonglong2*)(wb + (size_t)r * H_DIM);
            ulonglong2 v = *(const ulonglong2*)(wb + (size_t)r * H_DIM + 4);
            W2[r][0] = u.x; W2[r][1] = u.y; W2[r][2] = v.x; W2[r][3] = v.y;
        }
    }

    // ---- h registers init from h0 (this lane's 8 columns) ----
    unsigned long long h2[4];
    {
        const float* hp = h0 + warp * CHUNK + lane * 8;
        ulonglong2 u = *(const ulonglong2*)hp;
        ulonglong2 v = *(const ulonglong2*)(hp + 4);
        h2[0] = u.x; h2[1] = u.y; h2[2] = v.x; h2[3] = v.y;
    }

    // xi for this CTA's rows: warp 0, lanes 0..15 (one row each)
    float xi_cur = 0.f;
    if (warp == 0 && lane < 16) xi_cur = g_xi[row0 + lane];

    unsigned* my_ep   = &g_ep[(b >> 4) * 32 + (b & 15)];          // publish word
    unsigned* poll_ep = &g_ep[warp * 32 + (lane >> 1)];           // my producer

    const bool b4 = (lane & 16) != 0;
    const bool b3 = (lane & 8)  != 0;
    const bool b2 = (lane & 4)  != 0;
    const bool b1 = (lane & 2)  != 0;

    for (int t = 0; t < S_LEN; t++) {
        const int buf = t & 1;

        // prefetch xi for t+1 (hidden under matvec+reduce)
        float xi_nxt = 0.f;
        if (warp == 0 && lane < 16 && t + 1 < S_LEN)
            xi_nxt = g_xi[(size_t)(t + 1) * H_DIM + row0 + lane];

        // ---- matvec: 16 rows x 8 cols per lane, all in registers ----
        unsigned long long acc[16];
#pragma unroll
        for (int r = 0; r < 16; r++) {
            acc[r] = ffma2(W2[r][0], h2[0], 0ull);
            acc[r] = ffma2(W2[r][1], h2[1], acc[r]);
            acc[r] = ffma2(W2[r][2], h2[2], acc[r]);
            acc[r] = ffma2(W2[r][3], h2[3], acc[r]);
        }
        // fold k-halves, pack row pairs: q[j] = {row 2j, row 2j+1}
        unsigned long long q[8];
#pragma unroll
        for (int j = 0; j < 8; j++) {
            float l0, u0, l1, u1;
            asm("mov.b64 {%0, %1}, %2;" : "=f"(l0), "=f"(u0) : "l"(acc[2 * j]));
            asm("mov.b64 {%0, %1}, %2;" : "=f"(l1), "=f"(u1) : "l"(acc[2 * j + 1]));
            const float s0 = l0 + u0;
            const float s1 = l1 + u1;
            asm("mov.b64 %0, {%1, %2};" : "=l"(q[j]) : "f"(s0), "f"(s1));
        }

        // ---- halving-payload reduction: 9 shfls (R11-proven) ----
        unsigned long long n[4];
#pragma unroll
        for (int j = 0; j < 4; j++) {
            const unsigned long long keep = b4 ? q[j + 4] : q[j];
            const unsigned long long send = b4 ? q[j]     : q[j + 4];
            n[j] = addf2(keep, shflx2(send, 16));
        }
        unsigned long long m[2];
#pragma unroll
        for (int j = 0; j < 2; j++) {
            const unsigned long long keep = b3 ? n[j + 2] : n[j];
            const unsigned long long send = b3 ? n[j]     : n[j + 2];
            m[j] = addf2(keep, shflx2(send, 8));
        }
        unsigned long long p;
        {
            const unsigned long long keep = b2 ? m[1] : m[0];
            const unsigned long long send = b2 ? m[0] : m[1];
            p = addf2(keep, shflx2(send, 4));
        }
        float val;
        {
            float e, f;
            asm("mov.b64 {%0, %1}, %2;" : "=f"(e), "=f"(f) : "l"(p));
            const float keep = b1 ? f : e;
            const float send = b1 ? e : f;
            val = keep + __shfl_xor_sync(0xffffffffu, send, 2);
        }
        val += __shfl_xor_sync(0xffffffffu, val, 1);
        if ((lane & 1) == 0) part[buf][warp][lane >> 1] = val;

        __syncthreads();   // bar1: all partials of step t visible

        // ---- warp 0: cross-warp sum, tanh, coalesced publish, release ----
        if (warp == 0) {
            if (lane < 16) {
                const float s =
                    ((part[buf][0][lane] + part[buf][1][lane]) +
                     (part[buf][2][lane] + part[buf][3][lane])) +
                    ((part[buf][4][lane] + part[buf][5][lane]) +
                     (part[buf][6][lane] + part[buf][7][lane]));
                const float hn = tanh_fast(s + xi_cur);
                __stcg(g_rnn + (size_t)t * H_DIM + row0 + lane, hn);
            }
            __syncwarp();   // warp0's 16 stores happen-before lane0's release
            if (lane == 0) {
                asm volatile("st.release.gpu.global.u32 [%0], %1;"
                             :: "l"(my_ep), "r"((unsigned)(t + 1))
                             : "memory");
            }
        }
        xi_cur = xi_nxt;

        if (t + 1 < S_LEN) {
            // coalesced parallel-acquire poll: one 64B transaction / iter
            const unsigned want = (unsigned)(t + 1);
            unsigned v;
            bool ready;
            do {
                asm volatile("ld.acquire.gpu.global.u32 %0, [%1];"
                             : "=r"(v) : "l"(poll_ep) : "memory");
                ready = __all_sync(0xffffffffu, v >= want);
            } while (!ready);

            // load this lane's 8 h values straight into registers (L1 bypass)
            const float* hp = g_rnn + (size_t)t * H_DIM + warp * CHUNK + lane * 8;
            uint4 A = __ldcg((const uint4*)hp);
            uint4 B = __ldcg((const uint4*)(hp + 4));
            h2[0] = ((unsigned long long)A.y << 32) | A.x;
            h2[1] = ((unsigned long long)A.w << 32) | A.z;
            h2[2] = ((unsigned long long)B.y << 32) | B.x;
            h2[3] = ((unsigned long long)B.w << 32) | B.z;
            // no bar2: part[] is double-buffered (R11-proven)
        }
    }
}

// ---------------- Kernel 3: tag head + log_softmax (R5-proven) ----------------
#define OB_TOK     4
#define OB_THREADS 128

__global__ __launch_bounds__(OB_THREADS) void head_kernel(
    const float* __restrict__ W_out,
    const float* __restrict__ b_out,
    float*       __restrict__ out)
{
    __shared__ float shh[OB_TOK][H_DIM];
    __shared__ float ts[OB_TOK][T_TAGS];

    const int tid = threadIdx.x;
    const int s0  = blockIdx.x * OB_TOK;

    {
        const float4* src = (const float4*)(g_rnn + (size_t)s0 * H_DIM);
        float4*       dst = (float4*)&shh[0][0];
        for (int i = tid; i < OB_TOK * H_DIM / 4; i += OB_THREADS) dst[i] = src[i];
    }
    __syncthreads();

    if (tid < T_TAGS) {
        const float* w = W_out + (size_t)tid * H_DIM;
        float a0 = 0.f, a1 = 0.f, a2 = 0.f, a3 = 0.f;
        for (int c = 0; c < H_DIM; c += 4) {
            float4 w4 = *(const float4*)(w + c);
            float4 h0v = *(const float4*)&shh[0][c];
            float4 h1v = *(const float4*)&shh[1][c];
            float4 h2v = *(const float4*)&shh[2][c];
            float4 h3v = *(const float4*)&shh[3][c];
            a0 = fmaf(w4.x, h0v.x, a0); a0 = fmaf(w4.y, h0v.y, a0);
            a0 = fmaf(w4.z, h0v.z, a0); a0 = fmaf(w4.w, h0v.w, a0);
            a1 = fmaf(w4.x, h1v.x, a1); a1 = fmaf(w4.y, h1v.y, a1);
            a1 = fmaf(w4.z, h1v.z, a1); a1 = fmaf(w4.w, h1v.w, a1);
            a2 = fmaf(w4.x, h2v.x, a2); a2 = fmaf(w4.y, h2v.y, a2);
            a2 = fmaf(w4.z, h2v.z, a2); a2 = fmaf(w4.w, h2v.w, a2);
            a3 = fmaf(w4.x, h3v.x, a3); a3 = fmaf(w4.y, h3v.y, a3);
            a3 = fmaf(w4.z, h3v.z, a3); a3 = fmaf(w4.w, h3v.w, a3);
        }
        const float bo = b_out[tid];
        ts[0][tid] = a0 + bo;
        ts[1][tid] = a1 + bo;
        ts[2][tid] = a2 + bo;
        ts[3][tid] = a3 + bo;
    }
    __syncthreads();

    if (tid < OB_TOK) {
        float mx = -1e30f;
        for (int j = 0; j < T_TAGS; j++) mx = fmaxf(mx, ts[tid][j]);
        float sum = 0.f;
        for (int j = 0; j < T_TAGS; j++) sum += expf(ts[tid][j] - mx);
        const float lse = mx + logf(sum);
        float* o = out + (size_t)(s0 + tid) * T_TAGS;
        for (int j = 0; j < T_TAGS; j++) o[j] = ts[tid][j] - lse;
    }
}

// ---------------- launch ----------------
extern "C" void kernel_launch(void* const* d_in, const int* in_sizes, int n_in,
                              void* d_out, int out_size)
{
    const int*   sent  = (const int*)  d_in[0];
    const float* emb   = (const float*)d_in[1];
    const float* W_ih  = (const float*)d_in[2];
    const float* W_hh  = (const float*)d_in[3];
    const float* b_ih  = (const float*)d_in[4];
    const float* b_hh  = (const float*)d_in[5];
    const float* W_out = (const float*)d_in[6];
    const float* b_out = (const float*)d_in[7];
    const float* h0    = (const float*)d_in[8];
    float* out = (float*)d_out;

    (void)in_sizes; (void)n_in; (void)out_size;

    init_ep_kernel<<<1, 256>>>();

    dim3 ggrid(H_DIM / GBN, S_LEN / GBM);
    xi_gemm_kernel<<<ggrid, 256>>>(sent, emb, W_ih, b_ih, b_hh);

    rnn_kernel<<<RB_NBLK, RB_THREADS>>>(W_hh, h0);

    head_kernel<<<S_LEN / OB_TOK, OB_THREADS>>>(W_out, b_out, out);
}

// round 14
// speedup vs baseline: 2.6106x; 2.6106x over previous
#include <cuda_runtime.h>
#include <math.h>
#include <stdint.h>

#define S_LEN   8192
#define E_DIM   1024
#define H_DIM   2048
#define T_TAGS  50

// ---------------- persistent recurrence config ----------------
#define RB_NBLK    128
#define RB_ROWS    16          // H rows per block (128*16 = 2048)
#define RB_THREADS 256         // 8 warps
#define N_GRP      8           // h chunks (one per warp)
#define GRP_CTAS   (RB_NBLK / N_GRP)    // 16 producer CTAs per chunk
#define CHUNK      (H_DIM / N_GRP)      // 256 floats per chunk

// ---------------- scratch (static device memory; no allocs) ----------------
__device__ float g_xi[(size_t)S_LEN * H_DIM];    // 64 MB
__device__ float g_rnn[(size_t)S_LEN * H_DIM];   // 64 MB
__device__ unsigned g_cnt8[N_GRP * 32];          // 8 counters, 128B apart (R11-proven)

__global__ void init_cnt_kernel() {
    if (threadIdx.x < N_GRP * 32) g_cnt8[threadIdx.x] = 0u;
}

// ---------------- packed f32x2 helpers ----------------
__device__ __forceinline__ unsigned long long ffma2(unsigned long long a,
                                                    unsigned long long b,
                                                    unsigned long long c) {
    unsigned long long d;
    asm("fma.rn.f32x2 %0, %1, %2, %3;" : "=l"(d) : "l"(a), "l"(b), "l"(c));
    return d;
}
__device__ __forceinline__ unsigned long long addf2(unsigned long long a,
                                                    unsigned long long b) {
    unsigned long long d;
    asm("add.rn.f32x2 %0, %1, %2;" : "=l"(d) : "l"(a), "l"(b));
    return d;
}
// broadcast-pack one float into both halves of an f32x2
__device__ __forceinline__ unsigned long long packdup(float a) {
    unsigned long long d;
    asm("mov.b64 %0, {%1, %1};" : "=l"(d) : "f"(a));
    return d;
}
// 64-bit shfl.xor via two 32-bit shfls
__device__ __forceinline__ unsigned long long shflx2(unsigned long long v,
                                                     int mask) {
    unsigned lo = (unsigned)v, hi = (unsigned)(v >> 32);
    lo = __shfl_xor_sync(0xffffffffu, lo, mask);
    hi = __shfl_xor_sync(0xffffffffu, hi, mask);
    return ((unsigned long long)hi << 32) | lo;
}

// fast tanh: 1 - 2/(e^{2x}+1); inf-safe, ~1e-6 rel err (budget is 1e-3)
__device__ __forceinline__ float tanh_fast(float x) {
    const float e2 = __expf(2.f * x);
    return 1.f - __fdividef(2.f, e2 + 1.f);
}

// ---------------- Kernel 1: fused embedding gather + xi GEMM ----------------
// R14: inner product packed into fma.rn.f32x2 (j-pairs). Per-output FMA
// chains are elementwise-identical to the scalar version -> bit-identical xi.
#define GBM 64
#define GBN 64
#define GBK 16

__global__ __launch_bounds__(256) void xi_gemm_kernel(
    const int*   __restrict__ sent,
    const float* __restrict__ emb,
    const float* __restrict__ W_ih,
    const float* __restrict__ b_ih,
    const float* __restrict__ b_hh)
{
    __shared__ float As[GBM][GBK + 1];
    __shared__ __align__(16) float Bs[GBK][GBN + 4];
    __shared__ int   sidx[GBM];

    const int tid = threadIdx.x;
    const int m0  = blockIdx.y * GBM;
    const int n0  = blockIdx.x * GBN;

    if (tid < GBM) sidx[tid] = sent[m0 + tid];
    __syncthreads();

    const int lr = tid >> 2;
    const int lk = (tid & 3) * 4;
    const int tx = tid & 15;
    const int ty = tid >> 4;

    // accp[i][0] = {acc[i][0], acc[i][1]}, accp[i][1] = {acc[i][2], acc[i][3]}
    unsigned long long accp[4][2];
#pragma unroll
    for (int i = 0; i < 4; i++) { accp[i][0] = 0ull; accp[i][1] = 0ull; }

    const float* arow = emb  + (size_t)sidx[lr] * E_DIM;
    const float* brow = W_ih + (size_t)(n0 + lr) * E_DIM;

    for (int kt = 0; kt < E_DIM; kt += GBK) {
        float4 av = *(const float4*)(arow + kt + lk);
        float4 bv = *(const float4*)(brow + kt + lk);
        As[lr][lk + 0] = av.x; As[lr][lk + 1] = av.y;
        As[lr][lk + 2] = av.z; As[lr][lk + 3] = av.w;
        Bs[lk + 0][lr] = bv.x; Bs[lk + 1][lr] = bv.y;
        Bs[lk + 2][lr] = bv.z; Bs[lk + 3][lr] = bv.w;
        __syncthreads();

#pragma unroll
        for (int k = 0; k < GBK; k++) {
            const unsigned long long pa0 = packdup(As[ty * 4 + 0][k]);
            const unsigned long long pa1 = packdup(As[ty * 4 + 1][k]);
            const unsigned long long pa2 = packdup(As[ty * 4 + 2][k]);
            const unsigned long long pa3 = packdup(As[ty * 4 + 3][k]);
            const ulonglong2 b2 = *(const ulonglong2*)&Bs[k][tx * 4];
            accp[0][0] = ffma2(pa0, b2.x, accp[0][0]);
            accp[0][1] = ffma2(pa0, b2.y, accp[0][1]);
            accp[1][0] = ffma2(pa1, b2.x, accp[1][0]);
            accp[1][1] = ffma2(pa1, b2.y, accp[1][1]);
            accp[2][0] = ffma2(pa2, b2.x, accp[2][0]);
            accp[2][1] = ffma2(pa2, b2.y, accp[2][1]);
            accp[3][0] = ffma2(pa3, b2.x, accp[3][0]);
            accp[3][1] = ffma2(pa3, b2.y, accp[3][1]);
        }
        __syncthreads();
    }

#pragma unroll
    for (int i = 0; i < 4; i++) {
        float a0, a1, a2, a3;
        asm("mov.b64 {%0, %1}, %2;" : "=f"(a0), "=f"(a1) : "l"(accp[i][0]));
        asm("mov.b64 {%0, %1}, %2;" : "=f"(a2), "=f"(a3) : "l"(accp[i][1]));
        const int s = m0 + ty * 4 + i;
        const int h0 = n0 + tx * 4;
        g_xi[(size_t)s * H_DIM + h0 + 0] = a0 + b_ih[h0 + 0] + b_hh[h0 + 0];
        g_xi[(size_t)s * H_DIM + h0 + 1] = a1 + b_ih[h0 + 1] + b_hh[h0 + 1];
        g_xi[(size_t)s * H_DIM + h0 + 2] = a2 + b_ih[h0 + 2] + b_hh[h0 + 2];
        g_xi[(size_t)s * H_DIM + h0 + 3] = a3 + b_ih[h0 + 3] + b_hh[h0 + 3];
    }
}

// ---------------- Kernel 2: persistent Elman recurrence (R11 VERBATIM) ------
// Column-split register matvec + 9-shfl halving reduction + double-buffered
// part[] + fast tanh. Sync (bench-proven best): per-group red.release
// counters, per-warp BROADCAST acquire-poll (all lanes, one line), __ldcg h.
__global__ void __launch_bounds__(RB_THREADS, 1) rnn_kernel(
    const float* __restrict__ W_hh,
    const float* __restrict__ h0)
{
    __shared__ __align__(16) float part[2][N_GRP][16];  // double-buffered

    const int b    = blockIdx.x;
    const int tid  = threadIdx.x;
    const int warp = tid >> 5;
    const int lane = tid & 31;
    const int row0 = b * RB_ROWS;

    // ---- W registers: rows 0..15, cols warp*256 + lane*8 .. +7 ----
    unsigned long long W2[16][4];
    {
        const float* wb = W_hh + (size_t)row0 * H_DIM + warp * CHUNK + lane * 8;
#pragma unroll
        for (int r = 0; r < 16; r++) {
            ulonglong2 u = *(const ulonglong2*)(wb + (size_t)r * H_DIM);
            ulonglong2 v = *(const ulonglong2*)(wb + (size_t)r * H_DIM + 4);
            W2[r][0] = u.x; W2[r][1] = u.y; W2[r][2] = v.x; W2[r][3] = v.y;
        }
    }

    // ---- h registers init from h0 (this lane's 8 columns) ----
    unsigned long long h2[4];
    {
        const float* hp = h0 + warp * CHUNK + lane * 8;
        ulonglong2 u = *(const ulonglong2*)hp;
        ulonglong2 v = *(const ulonglong2*)(hp + 4);
        h2[0] = u.x; h2[1] = u.y; h2[2] = v.x; h2[3] = v.y;
    }

    // xi for this CTA's rows: warp 0, lanes 0..15 (one row each)
    float xi_cur = 0.f;
    if (warp == 0 && lane < 16) xi_cur = g_xi[row0 + lane];

    unsigned* my_cnt   = &g_cnt8[(b >> 4) * 32];   // this CTA's group counter
    unsigned* poll_cnt = &g_cnt8[warp * 32];       // counter of chunk `warp`

    const bool b4 = (lane & 16) != 0;
    const bool b3 = (lane & 8)  != 0;
    const bool b2 = (lane & 4)  != 0;
    const bool b1 = (lane & 2)  != 0;

    for (int t = 0; t < S_LEN; t++) {
        const int buf = t & 1;

        // prefetch xi for t+1 (hidden under matvec+reduce)
        float xi_nxt = 0.f;
        if (warp == 0 && lane < 16 && t + 1 < S_LEN)
            xi_nxt = g_xi[(size_t)(t + 1) * H_DIM + row0 + lane];

        // ---- matvec: 16 rows x 8 cols per lane, all in registers ----
        unsigned long long acc[16];
#pragma unroll
        for (int r = 0; r < 16; r++) {
            acc[r] = ffma2(W2[r][0], h2[0], 0ull);
            acc[r] = ffma2(W2[r][1], h2[1], acc[r]);
            acc[r] = ffma2(W2[r][2], h2[2], acc[r]);
            acc[r] = ffma2(W2[r][3], h2[3], acc[r]);
        }
        // fold k-halves, pack row pairs: q[j] = {row 2j, row 2j+1}
        unsigned long long q[8];
#pragma unroll
        for (int j = 0; j < 8; j++) {
            float l0, u0, l1, u1;
            asm("mov.b64 {%0, %1}, %2;" : "=f"(l0), "=f"(u0) : "l"(acc[2 * j]));
            asm("mov.b64 {%0, %1}, %2;" : "=f"(l1), "=f"(u1) : "l"(acc[2 * j + 1]));
            const float s0 = l0 + u0;
            const float s1 = l1 + u1;
            asm("mov.b64 %0, {%1, %2};" : "=l"(q[j]) : "f"(s0), "f"(s1));
        }

        // ---- halving-payload reduction: 9 shfls (R11-proven) ----
        unsigned long long n[4];
#pragma unroll
        for (int j = 0; j < 4; j++) {
            const unsigned long long keep = b4 ? q[j + 4] : q[j];
            const unsigned long long send = b4 ? q[j]     : q[j + 4];
            n[j] = addf2(keep, shflx2(send, 16));
        }
        unsigned long long m[2];
#pragma unroll
        for (int j = 0; j < 2; j++) {
            const unsigned long long keep = b3 ? n[j + 2] : n[j];
            const unsigned long long send = b3 ? n[j]     : n[j + 2];
            m[j] = addf2(keep, shflx2(send, 8));
        }
        unsigned long long p;
        {
            const unsigned long long keep = b2 ? m[1] : m[0];
            const unsigned long long send = b2 ? m[0] : m[1];
            p = addf2(keep, shflx2(send, 4));
        }
        float val;
        {
            float e, f;
            asm("mov.b64 {%0, %1}, %2;" : "=f"(e), "=f"(f) : "l"(p));
            const float keep = b1 ? f : e;
            const float send = b1 ? e : f;
            val = keep + __shfl_xor_sync(0xffffffffu, send, 2);
        }
        val += __shfl_xor_sync(0xffffffffu, val, 1);
        if ((lane & 1) == 0) part[buf][warp][lane >> 1] = val;

        __syncthreads();   // bar1: all partials of step t visible

        // ---- warp 0: cross-warp sum, tanh, coalesced publish, release ----
        if (warp == 0) {
            if (lane < 16) {
                const float s =
                    ((part[buf][0][lane] + part[buf][1][lane]) +
                     (part[buf][2][lane] + part[buf][3][lane])) +
                    ((part[buf][4][lane] + part[buf][5][lane]) +
                     (part[buf][6][lane] + part[buf][7][lane]));
                const float hn = tanh_fast(s + xi_cur);
                __stcg(g_rnn + (size_t)t * H_DIM + row0 + lane, hn);
            }
            __syncwarp();   // warp0's 16 stores happen-before lane0's release
            if (lane == 0) {
                asm volatile("red.release.gpu.global.add.u32 [%0], %1;"
                             :: "l"(my_cnt), "r"(1u) : "memory");
            }
        }
        xi_cur = xi_nxt;

        if (t + 1 < S_LEN) {
            // broadcast acquire-poll of chunk `warp`'s counter (R11-proven)
            const unsigned want = (unsigned)(GRP_CTAS * (t + 1));
            unsigned v;
            do {
                asm volatile("ld.acquire.gpu.global.u32 %0, [%1];"
                             : "=r"(v) : "l"(poll_cnt) : "memory");
            } while (v < want);

            // load this lane's 8 h values straight into registers (L1 bypass)
            const float* hp = g_rnn + (size_t)t * H_DIM + warp * CHUNK + lane * 8;
            uint4 A = __ldcg((const uint4*)hp);
            uint4 B = __ldcg((const uint4*)(hp + 4));
            h2[0] = ((unsigned long long)A.y << 32) | A.x;
            h2[1] = ((unsigned long long)A.w << 32) | A.z;
            h2[2] = ((unsigned long long)B.y << 32) | B.x;
            h2[3] = ((unsigned long long)B.w << 32) | B.z;
            // no bar2: part[] is double-buffered (R11-proven)
        }
    }
}

// ---------------- Kernel 3: tag head + log_softmax (R5-proven) ----------------
#define OB_TOK     4
#define OB_THREADS 128

__global__ __launch_bounds__(OB_THREADS) void head_kernel(
    const float* __restrict__ W_out,
    const float* __restrict__ b_out,
    float*       __restrict__ out)
{
    __shared__ float shh[OB_TOK][H_DIM];
    __shared__ float ts[OB_TOK][T_TAGS];

    const int tid = threadIdx.x;
    const int s0  = blockIdx.x * OB_TOK;

    {
        const float4* src = (const float4*)(g_rnn + (size_t)s0 * H_DIM);
        float4*       dst = (float4*)&shh[0][0];
        for (int i = tid; i < OB_TOK * H_DIM / 4; i += OB_THREADS) dst[i] = src[i];
    }
    __syncthreads();

    if (tid < T_TAGS) {
        const float* w = W_out + (size_t)tid * H_DIM;
        float a0 = 0.f, a1 = 0.f, a2 = 0.f, a3 = 0.f;
        for (int c = 0; c < H_DIM; c += 4) {
            float4 w4 = *(const float4*)(w + c);
            float4 h0v = *(const float4*)&shh[0][c];
            float4 h1v = *(const float4*)&shh[1][c];
            float4 h2v = *(const float4*)&shh[2][c];
            float4 h3v = *(const float4*)&shh[3][c];
            a0 = fmaf(w4.x, h0v.x, a0); a0 = fmaf(w4.y, h0v.y, a0);
            a0 = fmaf(w4.z, h0v.z, a0); a0 = fmaf(w4.w, h0v.w, a0);
            a1 = fmaf(w4.x, h1v.x, a1); a1 = fmaf(w4.y, h1v.y, a1);
            a1 = fmaf(w4.z, h1v.z, a1); a1 = fmaf(w4.w, h1v.w, a1);
            a2 = fmaf(w4.x, h2v.x, a2); a2 = fmaf(w4.y, h2v.y, a2);
            a2 = fmaf(w4.z, h2v.z, a2); a2 = fmaf(w4.w, h2v.w, a2);
            a3 = fmaf(w4.x, h3v.x, a3); a3 = fmaf(w4.y, h3v.y, a3);
            a3 = fmaf(w4.z, h3v.z, a3); a3 = fmaf(w4.w, h3v.w, a3);
        }
        const float bo = b_out[tid];
        ts[0][tid] = a0 + bo;
        ts[1][tid] = a1 + bo;
        ts[2][tid] = a2 + bo;
        ts[3][tid] = a3 + bo;
    }
    __syncthreads();

    if (tid < OB_TOK) {
        float mx = -1e30f;
        for (int j = 0; j < T_TAGS; j++) mx = fmaxf(mx, ts[tid][j]);
        float sum = 0.f;
        for (int j = 0; j < T_TAGS; j++) sum += expf(ts[tid][j] - mx);
        const float lse = mx + logf(sum);
        float* o = out + (size_t)(s0 + tid) * T_TAGS;
        for (int j = 0; j < T_TAGS; j++) o[j] = ts[tid][j] - lse;
    }
}

// ---------------- launch ----------------
extern "C" void kernel_launch(void* const* d_in, const int* in_sizes, int n_in,
                              void* d_out, int out_size)
{
    const int*   sent  = (const int*)  d_in[0];
    const float* emb   = (const float*)d_in[1];
    const float* W_ih  = (const float*)d_in[2];
    const float* W_hh  = (const float*)d_in[3];
    const float* b_ih  = (const float*)d_in[4];
    const float* b_hh  = (const float*)d_in[5];
    const float* W_out = (const float*)d_in[6];
    const float* b_out = (const float*)d_in[7];
    const float* h0    = (const float*)d_in[8];
    float* out = (float*)d_out;

    (void)in_sizes; (void)n_in; (void)out_size;

    init_cnt_kernel<<<1, 256>>>();

    dim3 ggrid(H_DIM / GBN, S_LEN / GBM);
    xi_gemm_kernel<<<ggrid, 256>>>(sent, emb, W_ih, b_ih, b_hh);

    rnn_kernel<<<RB_NBLK, RB_THREADS>>>(W_hh, h0);

    head_kernel<<<S_LEN / OB_TOK, OB_THREADS>>>(W_out, b_out, out);
}

// round 15
// speedup vs baseline: 2.6315x; 1.0080x over previous
#include <cuda_runtime.h>
#include <math.h>
#include <stdint.h>

#define S_LEN   8192
#define E_DIM   1024
#define H_DIM   2048
#define T_TAGS  50

// ---------------- persistent recurrence config ----------------
#define RB_NBLK    128
#define RB_ROWS    16          // H rows per block (128*16 = 2048)
#define RB_THREADS 256         // 8 warps
#define N_GRP      8           // h chunks (one per warp)
#define GRP_CTAS   (RB_NBLK / N_GRP)    // 16 producer CTAs per chunk
#define CHUNK      (H_DIM / N_GRP)      // 256 floats per chunk
#define N_SUB      4           // sub-counters per group (4 arrivals each)

// ---------------- scratch (static device memory; no allocs) ----------------
__device__ float g_xi[(size_t)S_LEN * H_DIM];    // 64 MB
__device__ float g_rnn[(size_t)S_LEN * H_DIM];   // 64 MB
// per-group 128B region; words 0..3 = sub-counters (one 16B/32B-sector span).
// 4 RMW arrivals per address instead of 16 -> ~3x less LTS atomic drain,
// while the consumer poll remains ONE sector read per warp per iteration.
__device__ __align__(128) unsigned g_cnt8[N_GRP * 32];

__global__ void init_cnt_kernel() {
    if (threadIdx.x < N_GRP * 32) g_cnt8[threadIdx.x] = 0u;
}

// ---------------- packed f32x2 helpers ----------------
__device__ __forceinline__ unsigned long long ffma2(unsigned long long a,
                                                    unsigned long long b,
                                                    unsigned long long c) {
    unsigned long long d;
    asm("fma.rn.f32x2 %0, %1, %2, %3;" : "=l"(d) : "l"(a), "l"(b), "l"(c));
    return d;
}
__device__ __forceinline__ unsigned long long addf2(unsigned long long a,
                                                    unsigned long long b) {
    unsigned long long d;
    asm("add.rn.f32x2 %0, %1, %2;" : "=l"(d) : "l"(a), "l"(b));
    return d;
}
// 64-bit shfl.xor via two 32-bit shfls
__device__ __forceinline__ unsigned long long shflx2(unsigned long long v,
                                                     int mask) {
    unsigned lo = (unsigned)v, hi = (unsigned)(v >> 32);
    lo = __shfl_xor_sync(0xffffffffu, lo, mask);
    hi = __shfl_xor_sync(0xffffffffu, hi, mask);
    return ((unsigned long long)hi << 32) | lo;
}

// fast tanh: 1 - 2/(e^{2x}+1); inf-safe, ~1e-6 rel err (budget is 1e-3)
__device__ __forceinline__ float tanh_fast(float x) {
    const float e2 = __expf(2.f * x);
    return 1.f - __fdividef(2.f, e2 + 1.f);
}

// ---------------- Kernel 1: fused embedding gather + xi GEMM (R3-proven) ----
#define GBM 64
#define GBN 64
#define GBK 16

__global__ __launch_bounds__(256) void xi_gemm_kernel(
    const int*   __restrict__ sent,
    const float* __restrict__ emb,
    const float* __restrict__ W_ih,
    const float* __restrict__ b_ih,
    const float* __restrict__ b_hh)
{
    __shared__ float As[GBM][GBK + 1];
    __shared__ float Bs[GBK][GBN + 4];
    __shared__ int   sidx[GBM];

    const int tid = threadIdx.x;
    const int m0  = blockIdx.y * GBM;
    const int n0  = blockIdx.x * GBN;

    if (tid < GBM) sidx[tid] = sent[m0 + tid];
    __syncthreads();

    const int lr = tid >> 2;
    const int lk = (tid & 3) * 4;
    const int tx = tid & 15;
    const int ty = tid >> 4;

    float acc[4][4];
#pragma unroll
    for (int i = 0; i < 4; i++)
#pragma unroll
        for (int j = 0; j < 4; j++) acc[i][j] = 0.f;

    const float* arow = emb  + (size_t)sidx[lr] * E_DIM;
    const float* brow = W_ih + (size_t)(n0 + lr) * E_DIM;

    for (int kt = 0; kt < E_DIM; kt += GBK) {
        float4 av = *(const float4*)(arow + kt + lk);
        float4 bv = *(const float4*)(brow + kt + lk);
        As[lr][lk + 0] = av.x; As[lr][lk + 1] = av.y;
        As[lr][lk + 2] = av.z; As[lr][lk + 3] = av.w;
        Bs[lk + 0][lr] = bv.x; Bs[lk + 1][lr] = bv.y;
        Bs[lk + 2][lr] = bv.z; Bs[lk + 3][lr] = bv.w;
        __syncthreads();

#pragma unroll
        for (int k = 0; k < GBK; k++) {
            float a0 = As[ty * 4 + 0][k];
            float a1 = As[ty * 4 + 1][k];
            float a2 = As[ty * 4 + 2][k];
            float a3 = As[ty * 4 + 3][k];
            float4 b4 = *(const float4*)&Bs[k][tx * 4];
            acc[0][0] = fmaf(a0, b4.x, acc[0][0]);
            acc[0][1] = fmaf(a0, b4.y, acc[0][1]);
            acc[0][2] = fmaf(a0, b4.z, acc[0][2]);
            acc[0][3] = fmaf(a0, b4.w, acc[0][3]);
            acc[1][0] = fmaf(a1, b4.x, acc[1][0]);
            acc[1][1] = fmaf(a1, b4.y, acc[1][1]);
            acc[1][2] = fmaf(a1, b4.z, acc[1][2]);
            acc[1][3] = fmaf(a1, b4.w, acc[1][3]);
            acc[2][0] = fmaf(a2, b4.x, acc[2][0]);
            acc[2][1] = fmaf(a2, b4.y, acc[2][1]);
            acc[2][2] = fmaf(a2, b4.z, acc[2][2]);
            acc[2][3] = fmaf(a2, b4.w, acc[2][3]);
            acc[3][0] = fmaf(a3, b4.x, acc[3][0]);
            acc[3][1] = fmaf(a3, b4.y, acc[3][1]);
            acc[3][2] = fmaf(a3, b4.z, acc[3][2]);
            acc[3][3] = fmaf(a3, b4.w, acc[3][3]);
        }
        __syncthreads();
    }

#pragma unroll
    for (int j = 0; j < 4; j++) {
        const int h = n0 + tx * 4 + j;
        const float bias = b_ih[h] + b_hh[h];
#pragma unroll
        for (int i = 0; i < 4; i++) {
            const int s = m0 + ty * 4 + i;
            g_xi[(size_t)s * H_DIM + h] = acc[i][j] + bias;
        }
    }
}

// ---------------- Kernel 2: persistent Elman recurrence ----------------
// R11 compute path verbatim. Sync delta (only change): each group's counter
// is split into 4 sub-counters within one 16B span. Producer CTA b REDs
// sub-word (b&3) -> 4 same-address arrivals instead of 16 (less LTS atomic
// serialization). Consumer warp w: lane l acquires sub-word ((l>>1)&3) —
// the sub-counter containing lane l's OWN producer CTA (position l>>1),
// so per-lane release/acquire pairing is exact; poll = one sector/warp/iter.
__global__ void __launch_bounds__(RB_THREADS, 1) rnn_kernel(
    const float* __restrict__ W_hh,
    const float* __restrict__ h0)
{
    __shared__ __align__(16) float part[2][N_GRP][16];  // double-buffered

    const int b    = blockIdx.x;
    const int tid  = threadIdx.x;
    const int warp = tid >> 5;
    const int lane = tid & 31;
    const int row0 = b * RB_ROWS;

    // ---- W registers: rows 0..15, cols warp*256 + lane*8 .. +7 ----
    unsigned long long W2[16][4];
    {
        const float* wb = W_hh + (size_t)row0 * H_DIM + warp * CHUNK + lane * 8;
#pragma unroll
        for (int r = 0; r < 16; r++) {
            ulonglong2 u = *(const ulonglong2*)(wb + (size_t)r * H_DIM);
            ulonglong2 v = *(const ulonglong2*)(wb + (size_t)r * H_DIM + 4);
            W2[r][0] = u.x; W2[r][1] = u.y; W2[r][2] = v.x; W2[r][3] = v.y;
        }
    }

    // ---- h registers init from h0 (this lane's 8 columns) ----
    unsigned long long h2[4];
    {
        const float* hp = h0 + warp * CHUNK + lane * 8;
        ulonglong2 u = *(const ulonglong2*)hp;
        ulonglong2 v = *(const ulonglong2*)(hp + 4);
        h2[0] = u.x; h2[1] = u.y; h2[2] = v.x; h2[3] = v.y;
    }

    // xi for this CTA's rows: warp 0, lanes 0..15 (one row each)
    float xi_cur = 0.f;
    if (warp == 0 && lane < 16) xi_cur = g_xi[row0 + lane];

    // producer: group (b>>4), sub-counter (b&3)  [position (b&15), sub = pos&3]
    unsigned* my_cnt   = &g_cnt8[(b >> 4) * 32 + (b & 3)];
    // consumer: lane's producer CTA position = lane>>1; its sub = (lane>>1)&3
    unsigned* poll_cnt = &g_cnt8[warp * 32 + ((lane >> 1) & 3)];

    const bool b4 = (lane & 16) != 0;
    const bool b3 = (lane & 8)  != 0;
    const bool b2 = (lane & 4)  != 0;
    const bool b1 = (lane & 2)  != 0;

    for (int t = 0; t < S_LEN; t++) {
        const int buf = t & 1;

        // prefetch xi for t+1 (hidden under matvec+reduce)
        float xi_nxt = 0.f;
        if (warp == 0 && lane < 16 && t + 1 < S_LEN)
            xi_nxt = g_xi[(size_t)(t + 1) * H_DIM + row0 + lane];

        // ---- matvec: 16 rows x 8 cols per lane, all in registers ----
        unsigned long long acc[16];
#pragma unroll
        for (int r = 0; r < 16; r++) {
            acc[r] = ffma2(W2[r][0], h2[0], 0ull);
            acc[r] = ffma2(W2[r][1], h2[1], acc[r]);
            acc[r] = ffma2(W2[r][2], h2[2], acc[r]);
            acc[r] = ffma2(W2[r][3], h2[3], acc[r]);
        }
        // fold k-halves, pack row pairs: q[j] = {row 2j, row 2j+1}
        unsigned long long q[8];
#pragma unroll
        for (int j = 0; j < 8; j++) {
            float l0, u0, l1, u1;
            asm("mov.b64 {%0, %1}, %2;" : "=f"(l0), "=f"(u0) : "l"(acc[2 * j]));
            asm("mov.b64 {%0, %1}, %2;" : "=f"(l1), "=f"(u1) : "l"(acc[2 * j + 1]));
            const float s0 = l0 + u0;
            const float s1 = l1 + u1;
            asm("mov.b64 %0, {%1, %2};" : "=l"(q[j]) : "f"(s0), "f"(s1));
        }

        // ---- halving-payload reduction: 9 shfls (R11-proven) ----
        unsigned long long n[4];
#pragma unroll
        for (int j = 0; j < 4; j++) {
            const unsigned long long keep = b4 ? q[j + 4] : q[j];
            const unsigned long long send = b4 ? q[j]     : q[j + 4];
            n[j] = addf2(keep, shflx2(send, 16));
        }
        unsigned long long m[2];
#pragma unroll
        for (int j = 0; j < 2; j++) {
            const unsigned long long keep = b3 ? n[j + 2] : n[j];
            const unsigned long long send = b3 ? n[j]     : n[j + 2];
            m[j] = addf2(keep, shflx2(send, 8));
        }
        unsigned long long p;
        {
            const unsigned long long keep = b2 ? m[1] : m[0];
            const unsigned long long send = b2 ? m[0] : m[1];
            p = addf2(keep, shflx2(send, 4));
        }
        float val;
        {
            float e, f;
            asm("mov.b64 {%0, %1}, %2;" : "=f"(e), "=f"(f) : "l"(p));
            const float keep = b1 ? f : e;
            const float send = b1 ? e : f;
            val = keep + __shfl_xor_sync(0xffffffffu, send, 2);
        }
        val += __shfl_xor_sync(0xffffffffu, val, 1);
        if ((lane & 1) == 0) part[buf][warp][lane >> 1] = val;

        __syncthreads();   // bar1: all partials of step t visible

        // ---- warp 0: cross-warp sum, tanh, coalesced publish, release ----
        if (warp == 0) {
            if (lane < 16) {
                const float s =
                    ((part[buf][0][lane] + part[buf][1][lane]) +
                     (part[buf][2][lane] + part[buf][3][lane])) +
                    ((part[buf][4][lane] + part[buf][5][lane]) +
                     (part[buf][6][lane] + part[buf][7][lane]));
                const float hn = tanh_fast(s + xi_cur);
                __stcg(g_rnn + (size_t)t * H_DIM + row0 + lane, hn);
            }
            __syncwarp();   // warp0's 16 stores happen-before lane0's release
            if (lane == 0) {
                asm volatile("red.release.gpu.global.add.u32 [%0], %1;"
                             :: "l"(my_cnt), "r"(1u) : "memory");
            }
        }
        xi_cur = xi_nxt;

        if (t + 1 < S_LEN) {
            // sub-counter acquire-poll: 4 arrivals per word, one sector/warp
            const unsigned want = (unsigned)((GRP_CTAS / N_SUB) * (t + 1));
            unsigned v;
            bool ready;
            do {
                asm volatile("ld.acquire.gpu.global.u32 %0, [%1];"
                             : "=r"(v) : "l"(poll_cnt) : "memory");
                ready = __all_sync(0xffffffffu, v >= want);
            } while (!ready);

            // load this lane's 8 h values straight into registers (L1 bypass)
            const float* hp = g_rnn + (size_t)t * H_DIM + warp * CHUNK + lane * 8;
            uint4 A = __ldcg((const uint4*)hp);
            uint4 B = __ldcg((const uint4*)(hp + 4));
            h2[0] = ((unsigned long long)A.y << 32) | A.x;
            h2[1] = ((unsigned long long)A.w << 32) | A.z;
            h2[2] = ((unsigned long long)B.y << 32) | B.x;
            h2[3] = ((unsigned long long)B.w << 32) | B.z;
            // no bar2: part[] is double-buffered (R11-proven)
        }
    }
}

// ---------------- Kernel 3: tag head + log_softmax (R5-proven) ----------------
#define OB_TOK     4
#define OB_THREADS 128

__global__ __launch_bounds__(OB_THREADS) void head_kernel(
    const float* __restrict__ W_out,
    const float* __restrict__ b_out,
    float*       __restrict__ out)
{
    __shared__ float shh[OB_TOK][H_DIM];
    __shared__ float ts[OB_TOK][T_TAGS];

    const int tid = threadIdx.x;
    const int s0  = blockIdx.x * OB_TOK;

    {
        const float4* src = (const float4*)(g_rnn + (size_t)s0 * H_DIM);
        float4*       dst = (float4*)&shh[0][0];
        for (int i = tid; i < OB_TOK * H_DIM / 4; i += OB_THREADS) dst[i] = src[i];
    }
    __syncthreads();

    if (tid < T_TAGS) {
        const float* w = W_out + (size_t)tid * H_DIM;
        float a0 = 0.f, a1 = 0.f, a2 = 0.f, a3 = 0.f;
        for (int c = 0; c < H_DIM; c += 4) {
            float4 w4 = *(const float4*)(w + c);
            float4 h0v = *(const float4*)&shh[0][c];
            float4 h1v = *(const float4*)&shh[1][c];
            float4 h2v = *(const float4*)&shh[2][c];
            float4 h3v = *(const float4*)&shh[3][c];
            a0 = fmaf(w4.x, h0v.x, a0); a0 = fmaf(w4.y, h0v.y, a0);
            a0 = fmaf(w4.z, h0v.z, a0); a0 = fmaf(w4.w, h0v.w, a0);
            a1 = fmaf(w4.x, h1v.x, a1); a1 = fmaf(w4.y, h1v.y, a1);
            a1 = fmaf(w4.z, h1v.z, a1); a1 = fmaf(w4.w, h1v.w, a1);
            a2 = fmaf(w4.x, h2v.x, a2); a2 = fmaf(w4.y, h2v.y, a2);
            a2 = fmaf(w4.z, h2v.z, a2); a2 = fmaf(w4.w, h2v.w, a2);
            a3 = fmaf(w4.x, h3v.x, a3); a3 = fmaf(w4.y, h3v.y, a3);
            a3 = fmaf(w4.z, h3v.z, a3); a3 = fmaf(w4.w, h3v.w, a3);
        }
        const float bo = b_out[tid];
        ts[0][tid] = a0 + bo;
        ts[1][tid] = a1 + bo;
        ts[2][tid] = a2 + bo;
        ts[3][tid] = a3 + bo;
    }
    __syncthreads();

    if (tid < OB_TOK) {
        float mx = -1e30f;
        for (int j = 0; j < T_TAGS; j++) mx = fmaxf(mx, ts[tid][j]);
        float sum = 0.f;
        for (int j = 0; j < T_TAGS; j++) sum += expf(ts[tid][j] - mx);
        const float lse = mx + logf(sum);
        float* o = out + (size_t)(s0 + tid) * T_TAGS;
        for (int j = 0; j < T_TAGS; j++) o[j] = ts[tid][j] - lse;
    }
}

// ---------------- launch ----------------
extern "C" void kernel_launch(void* const* d_in, const int* in_sizes, int n_in,
                              void* d_out, int out_size)
{
    const int*   sent  = (const int*)  d_in[0];
    const float* emb   = (const float*)d_in[1];
    const float* W_ih  = (const float*)d_in[2];
    const float* W_hh  = (const float*)d_in[3];
    const float* b_ih  = (const float*)d_in[4];
    const float* b_hh  = (const float*)d_in[5];
    const float* W_out = (const float*)d_in[6];
    const float* b_out = (const float*)d_in[7];
    const float* h0    = (const float*)d_in[8];
    float* out = (float*)d_out;

    (void)in_sizes; (void)n_in; (void)out_size;

    init_cnt_kernel<<<1, 256>>>();

    dim3 ggrid(H_DIM / GBN, S_LEN / GBM);
    xi_gemm_kernel<<<ggrid, 256>>>(sent, emb, W_ih, b_ih, b_hh);

    rnn_kernel<<<RB_NBLK, RB_THREADS>>>(W_hh, h0);

    head_kernel<<<S_LEN / OB_TOK, OB_THREADS>>>(W_out, b_out, out);
}

// round 16
// speedup vs baseline: 2.6417x; 1.0039x over previous
#include <cuda_runtime.h>
#include <math.h>
#include <stdint.h>

#define S_LEN   8192
#define E_DIM   1024
#define H_DIM   2048
#define T_TAGS  50

// ---------------- persistent recurrence config ----------------
#define RB_NBLK    128
#define RB_ROWS    16          // H rows per block (128*16 = 2048)
#define RB_THREADS 256         // 8 warps
#define N_GRP      8           // h chunks (one per warp)
#define GRP_CTAS   (RB_NBLK / N_GRP)    // 16 producer CTAs per chunk
#define CHUNK      (H_DIM / N_GRP)      // 256 floats per chunk

// ---------------- scratch (static device memory; no allocs) ----------------
__device__ float g_rnn[(size_t)S_LEN * H_DIM];   // 64 MB
__device__ unsigned g_cnt8[N_GRP * 32];          // 8 counters, 128B apart (R11-proven)

__global__ void init_cnt_kernel() {
    if (threadIdx.x < N_GRP * 32) g_cnt8[threadIdx.x] = 0u;
}

// ---------------- packed f32x2 helpers ----------------
__device__ __forceinline__ unsigned long long ffma2(unsigned long long a,
                                                    unsigned long long b,
                                                    unsigned long long c) {
    unsigned long long d;
    asm("fma.rn.f32x2 %0, %1, %2, %3;" : "=l"(d) : "l"(a), "l"(b), "l"(c));
    return d;
}
__device__ __forceinline__ unsigned long long addf2(unsigned long long a,
                                                    unsigned long long b) {
    unsigned long long d;
    asm("add.rn.f32x2 %0, %1, %2;" : "=l"(d) : "l"(a), "l"(b));
    return d;
}
// 64-bit shfl.xor via two 32-bit shfls
__device__ __forceinline__ unsigned long long shflx2(unsigned long long v,
                                                     int mask) {
    unsigned lo = (unsigned)v, hi = (unsigned)(v >> 32);
    lo = __shfl_xor_sync(0xffffffffu, lo, mask);
    hi = __shfl_xor_sync(0xffffffffu, hi, mask);
    return ((unsigned long long)hi << 32) | lo;
}

// fast tanh: 1 - 2/(e^{2x}+1); inf-safe, ~1e-6 rel err (budget is 1e-3)
__device__ __forceinline__ float tanh_fast(float x) {
    const float e2 = __expf(2.f * x);
    return 1.f - __fdividef(2.f, e2 + 1.f);
}

// ---------------- fused Kernel: recurrence + on-the-fly xi ----------------
// Recurrence path = R11 VERBATIM (column-split register matvec, 9-shfl
// halving reduction, double-buffered part[], fast tanh, per-group
// red.release counters + broadcast acquire-poll + __ldcg h).
// NEW: xi rows are computed INSIDE the poll-idle window, 2 steps ahead:
//   - W_ih slice (16x1024, 64KB) lives in dynamic SMEM (loaded once)
//   - x_{t+2} = emb[sent[t+2]] read per-lane via __ldg (L2-broadcast row)
//   - per warp: 2 rows, 32 cols/lane -> 64 FFMA; f32x2 butterfly; lane0
//     adds biases and writes xi_buf[(t+2)&3]. Two bar1's separate write
//     from warp0's read at step t+2 (compiler-respected fences).
// This deletes the separate 1+ms xi GEMM kernel and all g_xi traffic.
__global__ void __launch_bounds__(RB_THREADS, 1) rnn_kernel(
    const float* __restrict__ W_hh,
    const float* __restrict__ h0,
    const int*   __restrict__ sent,
    const float* __restrict__ emb,
    const float* __restrict__ W_ih,
    const float* __restrict__ b_ih,
    const float* __restrict__ b_hh)
{
    extern __shared__ float smem[];
    float* w_s    = smem;                    // [16][1024] W_ih slice, 64KB
    float* xi_buf = smem + 16384;            // [4][16] xi ring
    float* part   = smem + 16384 + 64;       // [2][8][16] partials

    const int b    = blockIdx.x;
    const int tid  = threadIdx.x;
    const int warp = tid >> 5;
    const int lane = tid & 31;
    const int row0 = b * RB_ROWS;

    // ---- stage W_ih slice into SMEM (contiguous 16384 floats) ----
    {
        const float4* src = (const float4*)(W_ih + (size_t)row0 * E_DIM);
        float4*       dst = (float4*)w_s;
#pragma unroll
        for (int i = 0; i < 16; i++)
            dst[tid + i * RB_THREADS] = src[tid + i * RB_THREADS];
    }

    // ---- W_hh registers: rows 0..15, cols warp*256 + lane*8 .. +7 ----
    unsigned long long W2[16][4];
    {
        const float* wb = W_hh + (size_t)row0 * H_DIM + warp * CHUNK + lane * 8;
#pragma unroll
        for (int r = 0; r < 16; r++) {
            ulonglong2 u = *(const ulonglong2*)(wb + (size_t)r * H_DIM);
            ulonglong2 v = *(const ulonglong2*)(wb + (size_t)r * H_DIM + 4);
            W2[r][0] = u.x; W2[r][1] = u.y; W2[r][2] = v.x; W2[r][3] = v.y;
        }
    }

    // ---- h registers init from h0 (this lane's 8 columns) ----
    unsigned long long h2[4];
    {
        const float* hp = h0 + warp * CHUNK + lane * 8;
        ulonglong2 u = *(const ulonglong2*)hp;
        ulonglong2 v = *(const ulonglong2*)(hp + 4);
        h2[0] = u.x; h2[1] = u.y; h2[2] = v.x; h2[3] = v.y;
    }

    // per-warp output-row biases (used by lane 0 only)
    const float bias0 = b_ih[row0 + 2 * warp]     + b_hh[row0 + 2 * warp];
    const float bias1 = b_ih[row0 + 2 * warp + 1] + b_hh[row0 + 2 * warp + 1];

    __syncthreads();   // w_s visible before any xi compute

    // ---- xi compute helper (inlined twice): xi(row pair of this warp) ----
    // for target step ts, write xi_buf[ts&3][2w], [2w+1]
#define COMPUTE_XI(ts)                                                        \
    do {                                                                      \
        const int _idx = __ldg(&sent[(ts)]);                                  \
        const float* _xr = emb + (size_t)_idx * E_DIM + lane * 4;             \
        const float* _w0 = w_s + (2 * warp) * E_DIM + lane * 4;               \
        const float* _w1 = w_s + (2 * warp + 1) * E_DIM + lane * 4;           \
        float _c00 = 0.f, _c01 = 0.f, _c10 = 0.f, _c11 = 0.f;                 \
        _Pragma("unroll")                                                     \
        for (int _k = 0; _k < 8; _k++) {                                      \
            const float4 _xv = __ldg((const float4*)(_xr + _k * 128));        \
            const float4 _wa = *(const float4*)(_w0 + _k * 128);              \
            const float4 _wb = *(const float4*)(_w1 + _k * 128);              \
            _c00 = fmaf(_wa.x, _xv.x, _c00); _c01 = fmaf(_wa.y, _xv.y, _c01); \
            _c00 = fmaf(_wa.z, _xv.z, _c00); _c01 = fmaf(_wa.w, _xv.w, _c01); \
            _c10 = fmaf(_wb.x, _xv.x, _c10); _c11 = fmaf(_wb.y, _xv.y, _c11); \
            _c10 = fmaf(_wb.z, _xv.z, _c10); _c11 = fmaf(_wb.w, _xv.w, _c11); \
        }                                                                     \
        float _a0 = _c00 + _c01, _a1 = _c10 + _c11;                           \
        unsigned long long _pa;                                               \
        asm("mov.b64 %0, {%1, %2};" : "=l"(_pa) : "f"(_a0), "f"(_a1));        \
        _pa = addf2(_pa, shflx2(_pa, 16));                                    \
        _pa = addf2(_pa, shflx2(_pa, 8));                                     \
        _pa = addf2(_pa, shflx2(_pa, 4));                                     \
        _pa = addf2(_pa, shflx2(_pa, 2));                                     \
        _pa = addf2(_pa, shflx2(_pa, 1));                                     \
        if (lane == 0) {                                                      \
            float _s0, _s1;                                                   \
            asm("mov.b64 {%0, %1}, %2;" : "=f"(_s0), "=f"(_s1) : "l"(_pa));   \
            xi_buf[((ts) & 3) * 16 + 2 * warp]     = _s0 + bias0;             \
            xi_buf[((ts) & 3) * 16 + 2 * warp + 1] = _s1 + bias1;             \
        }                                                                     \
    } while (0)

    // prologue: xi for steps 0 and 1
    COMPUTE_XI(0);
    COMPUTE_XI(1);
    __syncthreads();   // xi_buf[0],[1] visible (also pre-loop fence)

    unsigned* my_cnt   = &g_cnt8[(b >> 4) * 32];   // this CTA's group counter
    unsigned* poll_cnt = &g_cnt8[warp * 32];       // counter of chunk `warp`

    const bool q4 = (lane & 16) != 0;
    const bool q3 = (lane & 8)  != 0;
    const bool q2 = (lane & 4)  != 0;
    const bool q1 = (lane & 2)  != 0;

    for (int t = 0; t < S_LEN; t++) {
        const int buf = t & 1;

        // ---- matvec: 16 rows x 8 cols per lane, all in registers ----
        unsigned long long acc[16];
#pragma unroll
        for (int r = 0; r < 16; r++) {
            acc[r] = ffma2(W2[r][0], h2[0], 0ull);
            acc[r] = ffma2(W2[r][1], h2[1], acc[r]);
            acc[r] = ffma2(W2[r][2], h2[2], acc[r]);
            acc[r] = ffma2(W2[r][3], h2[3], acc[r]);
        }
        // fold k-halves, pack row pairs: q[j] = {row 2j, row 2j+1}
        unsigned long long q[8];
#pragma unroll
        for (int j = 0; j < 8; j++) {
            float l0, u0, l1, u1;
            asm("mov.b64 {%0, %1}, %2;" : "=f"(l0), "=f"(u0) : "l"(acc[2 * j]));
            asm("mov.b64 {%0, %1}, %2;" : "=f"(l1), "=f"(u1) : "l"(acc[2 * j + 1]));
            const float s0 = l0 + u0;
            const float s1 = l1 + u1;
            asm("mov.b64 %0, {%1, %2};" : "=l"(q[j]) : "f"(s0), "f"(s1));
        }

        // ---- halving-payload reduction: 9 shfls (R11-proven) ----
        unsigned long long n[4];
#pragma unroll
        for (int j = 0; j < 4; j++) {
            const unsigned long long keep = q4 ? q[j + 4] : q[j];
            const unsigned long long send = q4 ? q[j]     : q[j + 4];
            n[j] = addf2(keep, shflx2(send, 16));
        }
        unsigned long long m[2];
#pragma unroll
        for (int j = 0; j < 2; j++) {
            const unsigned long long keep = q3 ? n[j + 2] : n[j];
            const unsigned long long send = q3 ? n[j]     : n[j + 2];
            m[j] = addf2(keep, shflx2(send, 8));
        }
        unsigned long long p;
        {
            const unsigned long long keep = q2 ? m[1] : m[0];
            const unsigned long long send = q2 ? m[0] : m[1];
            p = addf2(keep, shflx2(send, 4));
        }
        float val;
        {
            float e, f;
            asm("mov.b64 {%0, %1}, %2;" : "=f"(e), "=f"(f) : "l"(p));
            const float keep = q1 ? f : e;
            const float send = q1 ? e : f;
            val = keep + __shfl_xor_sync(0xffffffffu, send, 2);
        }
        val += __shfl_xor_sync(0xffffffffu, val, 1);
        if ((lane & 1) == 0) part[(buf * N_GRP + warp) * 16 + (lane >> 1)] = val;

        __syncthreads();   // bar1: all partials of step t visible

        // ---- warp 0: cross-warp sum, tanh, coalesced publish, release ----
        if (warp == 0) {
            if (lane < 16) {
                const float* pb = part + buf * N_GRP * 16;
                const float s =
                    ((pb[0 * 16 + lane] + pb[1 * 16 + lane]) +
                     (pb[2 * 16 + lane] + pb[3 * 16 + lane])) +
                    ((pb[4 * 16 + lane] + pb[5 * 16 + lane]) +
                     (pb[6 * 16 + lane] + pb[7 * 16 + lane]));
                const float hn = tanh_fast(s + xi_buf[(t & 3) * 16 + lane]);
                __stcg(g_rnn + (size_t)t * H_DIM + row0 + lane, hn);
            }
            __syncwarp();   // warp0's 16 stores happen-before lane0's release
            if (lane == 0) {
                asm volatile("red.release.gpu.global.add.u32 [%0], %1;"
                             :: "l"(my_cnt), "r"(1u) : "memory");
            }
        }

        // ---- idle-window work: xi for step t+2 (after release, before poll)
        if (t + 2 < S_LEN) COMPUTE_XI(t + 2);

        if (t + 1 < S_LEN) {
            // broadcast acquire-poll of chunk `warp`'s counter (R11-proven)
            const unsigned want = (unsigned)(GRP_CTAS * (t + 1));
            unsigned v;
            do {
                asm volatile("ld.acquire.gpu.global.u32 %0, [%1];"
                             : "=r"(v) : "l"(poll_cnt) : "memory");
            } while (v < want);

            // load this lane's 8 h values straight into registers (L1 bypass)
            const float* hp = g_rnn + (size_t)t * H_DIM + warp * CHUNK + lane * 8;
            uint4 A = __ldcg((const uint4*)hp);
            uint4 B = __ldcg((const uint4*)(hp + 4));
            h2[0] = ((unsigned long long)A.y << 32) | A.x;
            h2[1] = ((unsigned long long)A.w << 32) | A.z;
            h2[2] = ((unsigned long long)B.y << 32) | B.x;
            h2[3] = ((unsigned long long)B.w << 32) | B.z;
            // no bar2: part[] is double-buffered (R11-proven)
        }
    }
#undef COMPUTE_XI
}

// ---------------- Kernel 3: tag head + log_softmax (R5-proven) ----------------
#define OB_TOK     4
#define OB_THREADS 128

__global__ __launch_bounds__(OB_THREADS) void head_kernel(
    const float* __restrict__ W_out,
    const float* __restrict__ b_out,
    float*       __restrict__ out)
{
    __shared__ float shh[OB_TOK][H_DIM];
    __shared__ float ts[OB_TOK][T_TAGS];

    const int tid = threadIdx.x;
    const int s0  = blockIdx.x * OB_TOK;

    {
        const float4* src = (const float4*)(g_rnn + (size_t)s0 * H_DIM);
        float4*       dst = (float4*)&shh[0][0];
        for (int i = tid; i < OB_TOK * H_DIM / 4; i += OB_THREADS) dst[i] = src[i];
    }
    __syncthreads();

    if (tid < T_TAGS) {
        const float* w = W_out + (size_t)tid * H_DIM;
        float a0 = 0.f, a1 = 0.f, a2 = 0.f, a3 = 0.f;
        for (int c = 0; c < H_DIM; c += 4) {
            float4 w4 = *(const float4*)(w + c);
            float4 h0v = *(const float4*)&shh[0][c];
            float4 h1v = *(const float4*)&shh[1][c];
            float4 h2v = *(const float4*)&shh[2][c];
            float4 h3v = *(const float4*)&shh[3][c];
            a0 = fmaf(w4.x, h0v.x, a0); a0 = fmaf(w4.y, h0v.y, a0);
            a0 = fmaf(w4.z, h0v.z, a0); a0 = fmaf(w4.w, h0v.w, a0);
            a1 = fmaf(w4.x, h1v.x, a1); a1 = fmaf(w4.y, h1v.y, a1);
            a1 = fmaf(w4.z, h1v.z, a1); a1 = fmaf(w4.w, h1v.w, a1);
            a2 = fmaf(w4.x, h2v.x, a2); a2 = fmaf(w4.y, h2v.y, a2);
            a2 = fmaf(w4.z, h2v.z, a2); a2 = fmaf(w4.w, h2v.w, a2);
            a3 = fmaf(w4.x, h3v.x, a3); a3 = fmaf(w4.y, h3v.y, a3);
            a3 = fmaf(w4.z, h3v.z, a3); a3 = fmaf(w4.w, h3v.w, a3);
        }
        const float bo = b_out[tid];
        ts[0][tid] = a0 + bo;
        ts[1][tid] = a1 + bo;
        ts[2][tid] = a2 + bo;
        ts[3][tid] = a3 + bo;
    }
    __syncthreads();

    if (tid < OB_TOK) {
        float mx = -1e30f;
        for (int j = 0; j < T_TAGS; j++) mx = fmaxf(mx, ts[tid][j]);
        float sum = 0.f;
        for (int j = 0; j < T_TAGS; j++) sum += expf(ts[tid][j] - mx);
        const float lse = mx + logf(sum);
        float* o = out + (size_t)(s0 + tid) * T_TAGS;
        for (int j = 0; j < T_TAGS; j++) o[j] = ts[tid][j] - lse;
    }
}

// ---------------- launch ----------------
extern "C" void kernel_launch(void* const* d_in, const int* in_sizes, int n_in,
                              void* d_out, int out_size)
{
    const int*   sent  = (const int*)  d_in[0];
    const float* emb   = (const float*)d_in[1];
    const float* W_ih  = (const float*)d_in[2];
    const float* W_hh  = (const float*)d_in[3];
    const float* b_ih  = (const float*)d_in[4];
    const float* b_hh  = (const float*)d_in[5];
    const float* W_out = (const float*)d_in[6];
    const float* b_out = (const float*)d_in[7];
    const float* h0    = (const float*)d_in[8];
    float* out = (float*)d_out;

    (void)in_sizes; (void)n_in; (void)out_size;

    const size_t rsmem = (size_t)(16384 + 64 + 2 * N_GRP * 16) * sizeof(float);
    cudaFuncSetAttribute(rnn_kernel, cudaFuncAttributeMaxDynamicSharedMemorySize,
                         (int)rsmem);

    init_cnt_kernel<<<1, 256>>>();

    rnn_kernel<<<RB_NBLK, RB_THREADS, rsmem>>>(W_hh, h0, sent, emb,
                                               W_ih, b_ih, b_hh);

    head_kernel<<<S_LEN / OB_TOK, OB_THREADS>>>(W_out, b_out, out);
}